// round 1
// baseline (speedup 1.0000x reference)
#include <cuda_runtime.h>
#include <cuda_bf16.h>
#include <math.h>

// Problem constants (fixed by the dataset)
#define BATCH 16
#define SEQ   4096
#define DIM   1152
#define OUTL  1024
#define DIM4  (DIM / 4)        // 288 float4 per row
#define POOLED_ELEMS ((size_t)BATCH * OUTL * DIM)   // 18,874,368

// scale = sqrt(1152) / k^2 = sqrt(1152) / 4
#define POOL_SCALE 8.4852813742385702928f

// Scratch (device globals — no allocation allowed in kernel_launch)
__device__ int g_cnt[BATCH * OUTL];   // tokens per (batch, cell)
__device__ int g_off[BATCH * OUTL];   // exclusive offsets within batch
__device__ int g_list[BATCH * SEQ];   // token ids, CSR order per batch

// ---------------------------------------------------------------------------
// Kernel 1: per-batch  max_x -> divk,  bucket counts, block scan, CSR fill.
// grid = BATCH, block = 1024. Each thread handles 4 tokens (strided).
// ---------------------------------------------------------------------------
__global__ __launch_bounds__(1024, 1)
void build_kernel(const int2* __restrict__ pos)
{
    __shared__ int sCnt[OUTL];
    __shared__ int sWarp[32];

    const int b    = blockIdx.x;
    const int t    = threadIdx.x;
    const int lane = t & 31;
    const int wid  = t >> 5;

    const int2* p = pos + (size_t)b * SEQ;

    // Load this thread's 4 tokens' (x, y); track clamped max x.
    int2 v[4];
    int mymax = 0;
#pragma unroll
    for (int j = 0; j < 4; j++) {
        v[j] = p[t + j * 1024];
        mymax = max(mymax, max(v[j].x, 0));
    }

    // Block max-reduce -> sWarp[0]
#pragma unroll
    for (int o = 16; o > 0; o >>= 1)
        mymax = max(mymax, __shfl_down_sync(0xffffffffu, mymax, o));
    if (lane == 0) sWarp[wid] = mymax;
    __syncthreads();
    if (wid == 0) {
        int m = sWarp[lane];
#pragma unroll
        for (int o = 16; o > 0; o >>= 1)
            m = max(m, __shfl_down_sync(0xffffffffu, m, o));
        if (lane == 0) sWarp[0] = m;
    }
    __syncthreads();
    const int divk = (sWarp[0] + 1) >> 1;   // (max_x + 1) // k, k = 2
    __syncthreads();                        // everyone has divk before sWarp reuse

    // Phase 1: bucket counts in SMEM
    sCnt[t] = 0;
    __syncthreads();

    int idxv[4];
#pragma unroll
    for (int j = 0; j < 4; j++) {
        const int px = max(v[j].x, 0);
        const int py = max(v[j].y, 0);
        int id = (px >> 1) + divk * (py >> 1);
        if (id < 0 || id >= OUTL) id = -1;  // JAX drops OOB scatter indices
        idxv[j] = id;
        if (id >= 0) atomicAdd(&sCnt[id], 1);
    }
    __syncthreads();

    // Phase 2: block exclusive scan of the 1024 counts
    const int cnt = sCnt[t];
    int inc = cnt;
#pragma unroll
    for (int o = 1; o < 32; o <<= 1) {
        int n = __shfl_up_sync(0xffffffffu, inc, o);
        if (lane >= o) inc += n;
    }
    if (lane == 31) sWarp[wid] = inc;
    __syncthreads();
    if (wid == 0) {
        const int wv = sWarp[lane];
        int winc = wv;
#pragma unroll
        for (int o = 1; o < 32; o <<= 1) {
            int n = __shfl_up_sync(0xffffffffu, winc, o);
            if (lane >= o) winc += n;
        }
        sWarp[lane] = winc - wv;            // exclusive prefix of warp sums
    }
    __syncthreads();
    const int excl = inc - cnt + sWarp[wid];

    g_cnt[b * OUTL + t] = cnt;
    g_off[b * OUTL + t] = excl;

    // Phase 3: reuse sCnt as per-cell cursors, fill CSR list
    __syncthreads();
    sCnt[t] = excl;
    __syncthreads();
#pragma unroll
    for (int j = 0; j < 4; j++) {
        if (idxv[j] >= 0) {
            const int slot = atomicAdd(&sCnt[idxv[j]], 1);
            g_list[b * SEQ + slot] = t + j * 1024;
        }
    }
}

// ---------------------------------------------------------------------------
// Kernel 2: gather-pool. One block per output row, one float4 per thread.
// grid = BATCH*OUTL = 16384, block = DIM4 = 288 (9 warps).
// Fully coalesced row loads/stores; no atomics; every out element written.
// ---------------------------------------------------------------------------
__global__ __launch_bounds__(DIM4)
void pool_kernel(const float4* __restrict__ hidden,
                 const unsigned char* __restrict__ pad,
                 float4* __restrict__ out,
                 float* __restrict__ maskF,
                 unsigned char* __restrict__ maskB)
{
    const int bid = blockIdx.x;        // b*OUTL + cell
    const int b   = bid >> 10;
    const int t   = threadIdx.x;       // 0..287

    const int cnt = g_cnt[bid];
    const int off = g_off[bid] + b * SEQ;

    float4 acc = make_float4(0.f, 0.f, 0.f, 0.f);
    for (int i = 0; i < cnt; i++) {
        const int s = g_list[off + i];
        if (pad != nullptr && pad[(size_t)b * SEQ + s]) continue;  // zeroed rows
        const float4 hv = hidden[(size_t)(b * SEQ + s) * DIM4 + t];
        acc.x += hv.x; acc.y += hv.y; acc.z += hv.z; acc.w += hv.w;
    }

    acc.x *= POOL_SCALE; acc.y *= POOL_SCALE;
    acc.z *= POOL_SCALE; acc.w *= POOL_SCALE;

    out[(size_t)bid * DIM4 + t] = acc;

    if (t == 0) {
        const bool m = (cnt > 0);
        if (maskF) maskF[bid] = m ? 1.0f : 0.0f;
        if (maskB) maskB[bid] = m ? 1 : 0;
    }
}

// ---------------------------------------------------------------------------
extern "C" void kernel_launch(void* const* d_in, const int* in_sizes, int n_in,
                              void* d_out, int out_size)
{
    // Classify inputs by element count (robust to optional scalar output_length)
    const float*         hidden = nullptr;
    const int2*          pos    = nullptr;
    const unsigned char* pad    = nullptr;

    for (int i = 0; i < n_in; i++) {
        const long long sz = in_sizes[i];
        if (sz == (long long)BATCH * SEQ * DIM)      hidden = (const float*)d_in[i];
        else if (sz == (long long)BATCH * SEQ * 2)   pos    = (const int2*)d_in[i];
        else if (sz == (long long)BATCH * SEQ)       pad    = (const unsigned char*)d_in[i];
        // size-1 scalar (output_length) ignored — shapes are compile-time fixed
    }

    float* out = (float*)d_out;

    // Mask layout detection from out_size (elements of output dtype)
    float*         maskF = nullptr;
    unsigned char* maskB = nullptr;
    const long long extra = (long long)out_size - (long long)POOLED_ELEMS;
    if (extra == (long long)BATCH * OUTL) {
        maskF = out + POOLED_ELEMS;                       // mask as float32
    } else if (extra == (long long)BATCH * OUTL / 4) {
        maskB = (unsigned char*)(out + POOLED_ELEMS);     // mask as packed bytes
    }

    build_kernel<<<BATCH, 1024>>>(pos);
    pool_kernel<<<BATCH * OUTL, DIM4>>>((const float4*)hidden, pad,
                                        (float4*)out, maskF, maskB);
}